// round 5
// baseline (speedup 1.0000x reference)
#include <cuda_runtime.h>
#include <cuda_bf16.h>

#define X_DIM 4096
#define Z_DIM 64
#define N_HID 1024
#define ROW_LEN (X_DIM + 1)            // 4097 floats per W1 row
#define THREADS 256
#define NWARPS (THREADS / 32)          // 8
#define NSM 148
#define CTAS_PER_SM 3
#define NBLOCKS (NSM * CTAS_PER_SM)    // 444 — exactly one resident wave
#define NGWARPS (NBLOCKS * NWARPS)     // 3552 resident warps
#define ROWS_PER_TASK 8
#define TASKS_PER_HEAD (N_HID / ROWS_PER_TASK)   // 128
#define NTASKS (Z_DIM * TASKS_PER_HEAD)          // 8192
#define ROW_STRIDE TASKS_PER_HEAD      // 128: rows m, m+128, ... share align phase

// Seed output with b2 (d_out is poisoned; we atomically accumulate into it).
__global__ void mlp_init_kernel(const float* __restrict__ b2, float* __restrict__ out) {
    int i = threadIdx.x;
    if (i < Z_DIM) out[i] = b2[i];
}

__global__ __launch_bounds__(THREADS, CTAS_PER_SM)
void mlp_main_kernel(const float* __restrict__ x,
                     const float* __restrict__ z,
                     const float* __restrict__ W1,
                     const float* __restrict__ b1,
                     const float* __restrict__ W2,
                     float* __restrict__ out) {
    __shared__ float xs[X_DIM];

    const int tid  = threadIdx.x;
    const int wid  = tid >> 5;
    const int lane = tid & 31;
    const int gw   = blockIdx.x * NWARPS + wid;   // global warp id [0, 3552)

    // Stage x into shared memory once per block (vectorized, coalesced).
    {
        const float4* x4 = reinterpret_cast<const float4*>(x);
        float4* xs4 = reinterpret_cast<float4*>(xs);
        #pragma unroll
        for (int i = tid; i < X_DIM / 4; i += THREADS) {
            xs4[i] = x4[i];
        }
    }
    __syncthreads();

    // Warp-granular grid-stride over tasks. Task t: head k = t/128,
    // rows j = m + 128*r (r = 0..7), m = t%128. All 8 rows share the same
    // 16B alignment phase since 128 % 4 == 0 and row start elem = j*4097 ≡ j (mod 4).
    for (int t = gw; t < NTASKS; t += NGWARPS) {
        const int k = t >> 7;            // head index
        const int m = t & (TASKS_PER_HEAD - 1);
        const int p = (4 - (m & 3)) & 3; // head peel to reach 16B alignment

        const float* rows[ROWS_PER_TASK];
        #pragma unroll
        for (int r = 0; r < ROWS_PER_TASK; r++) {
            rows[r] = W1 + ((size_t)k * N_HID + (m + r * ROW_STRIDE)) * (size_t)ROW_LEN;
        }

        float s[ROWS_PER_TASK];
        #pragma unroll
        for (int r = 0; r < ROWS_PER_TASK; r++) s[r] = 0.0f;

        // Head peel: first p elements (p in 0..3), scalar, lanes < p.
        if (lane < p) {
            const float xv = xs[lane];
            #pragma unroll
            for (int r = 0; r < ROWS_PER_TASK; r++) {
                s[r] = fmaf(__ldg(rows[r] + lane), xv, s[r]);
            }
        }

        // Bulk: aligned float4 streams, 8 independent LDG.128 per iteration.
        const int nv4 = (X_DIM - p) >> 2;
        const float4* rp4[ROWS_PER_TASK];
        #pragma unroll
        for (int r = 0; r < ROWS_PER_TASK; r++) {
            rp4[r] = reinterpret_cast<const float4*>(rows[r] + p);
        }

        #pragma unroll 1
        for (int c = lane; c < nv4; c += 32) {
            const int e = p + 4 * c;
            const float xv0 = xs[e + 0];
            const float xv1 = xs[e + 1];
            const float xv2 = xs[e + 2];
            const float xv3 = xs[e + 3];
            #pragma unroll
            for (int r = 0; r < ROWS_PER_TASK; r++) {
                const float4 w = __ldg(rp4[r] + c);
                s[r] = fmaf(w.x, xv0, s[r]);
                s[r] = fmaf(w.y, xv1, s[r]);
                s[r] = fmaf(w.z, xv2, s[r]);
                s[r] = fmaf(w.w, xv3, s[r]);
            }
        }

        // Tail: remaining (X_DIM - p) % 4 elements, scalar, lanes < tail.
        const int tail  = (X_DIM - p) & 3;
        const int start = p + 4 * nv4;
        if (lane < tail) {
            const float xv = xs[start + lane];
            #pragma unroll
            for (int r = 0; r < ROWS_PER_TASK; r++) {
                s[r] = fmaf(__ldg(rows[r] + start + lane), xv, s[r]);
            }
        }

        // Warp-reduce each row, fold relu(h) * W2 on lane 0, one atomic per task.
        const float zk = __ldg(&z[k]);
        float facc = 0.0f;
        #pragma unroll
        for (int r = 0; r < ROWS_PER_TASK; r++) {
            float v = s[r];
            #pragma unroll
            for (int o = 16; o > 0; o >>= 1)
                v += __shfl_xor_sync(0xFFFFFFFFu, v, o);
            if (lane == 0) {
                const int j = m + r * ROW_STRIDE;
                float h = v + __ldg(rows[r] + X_DIM) * zk + __ldg(&b1[k * N_HID + j]);
                facc = fmaf(fmaxf(h, 0.0f), __ldg(&W2[k * N_HID + j]), facc);
            }
        }
        if (lane == 0) atomicAdd(&out[k], facc);
    }
}

extern "C" void kernel_launch(void* const* d_in, const int* in_sizes, int n_in,
                              void* d_out, int out_size) {
    const float* x  = (const float*)d_in[0];
    const float* z  = (const float*)d_in[1];
    const float* W1 = (const float*)d_in[2];
    const float* b1 = (const float*)d_in[3];
    const float* W2 = (const float*)d_in[4];
    const float* b2 = (const float*)d_in[5];
    float* out = (float*)d_out;

    mlp_init_kernel<<<1, 64>>>(b2, out);
    mlp_main_kernel<<<NBLOCKS, THREADS>>>(x, z, W1, b1, W2, out);
}

// round 6
// speedup vs baseline: 1.0015x; 1.0015x over previous
#include <cuda_runtime.h>
#include <cuda_bf16.h>

#define X_DIM 4096
#define Z_DIM 64
#define N_HID 1024
#define ROW_LEN (X_DIM + 1)            // 4097 floats per W1 row
#define THREADS 256
#define NWARPS (THREADS / 32)          // 8
#define NSM 148
#define CTAS_PER_SM 3
#define NBLOCKS (NSM * CTAS_PER_SM)    // 444 — exactly one resident wave
#define ROWS_PER_TASK 8
#define TASKS_PER_HEAD (N_HID / ROWS_PER_TASK)   // 128
#define NTASKS (Z_DIM * TASKS_PER_HEAD)          // 8192
#define ROW_STRIDE TASKS_PER_HEAD      // 128: rows m, m+128, ... share align phase

// Seed output with b2 (d_out is poisoned; we atomically accumulate into it).
__global__ void mlp_init_kernel(const float* __restrict__ b2, float* __restrict__ out) {
    int i = threadIdx.x;
    if (i < Z_DIM) out[i] = b2[i];
}

__global__ __launch_bounds__(THREADS, CTAS_PER_SM)
void mlp_main_kernel(const float* __restrict__ x,
                     const float* __restrict__ z,
                     const float* __restrict__ W1,
                     const float* __restrict__ b1,
                     const float* __restrict__ W2,
                     float* __restrict__ out) {
    __shared__ float xs[X_DIM];

    const int tid  = threadIdx.x;
    const int wid  = tid >> 5;
    const int lane = tid & 31;
    const int b    = blockIdx.x;

    // Stage x into shared memory once per block (vectorized, coalesced).
    {
        const float4* x4 = reinterpret_cast<const float4*>(x);
        float4* xs4 = reinterpret_cast<float4*>(xs);
        #pragma unroll
        for (int i = tid; i < X_DIM / 4; i += THREADS) {
            xs4[i] = x4[i];
        }
    }
    __syncthreads();

    // Block-granular task striding: block b owns tasks {b + i*NBLOCKS}.
    // Every block gets 18 or 19 tasks; with one resident wave (3 CTAs/SM on
    // every SM), per-SM totals are within 3% of each other. Warps round-robin
    // the block's tasks.
    for (int i = wid; ; i += NWARPS) {
        const int t = b + i * NBLOCKS;
        if (t >= NTASKS) break;

        const int k = t >> 7;            // head index = t / 128
        const int m = t & (TASKS_PER_HEAD - 1);
        const int p = (4 - (m & 3)) & 3; // head peel to reach 16B alignment
        // rows j = m + 128*r share one 16B phase (row start elem = j*4097 ≡ j mod 4)

        const float* rows[ROWS_PER_TASK];
        #pragma unroll
        for (int r = 0; r < ROWS_PER_TASK; r++) {
            rows[r] = W1 + ((size_t)k * N_HID + (m + r * ROW_STRIDE)) * (size_t)ROW_LEN;
        }

        float s[ROWS_PER_TASK];
        #pragma unroll
        for (int r = 0; r < ROWS_PER_TASK; r++) s[r] = 0.0f;

        // Head peel: first p elements (p in 0..3), scalar, lanes < p.
        if (lane < p) {
            const float xv = xs[lane];
            #pragma unroll
            for (int r = 0; r < ROWS_PER_TASK; r++) {
                s[r] = fmaf(__ldg(rows[r] + lane), xv, s[r]);
            }
        }

        // Bulk: aligned float4 streams, 8 independent LDG.128 per iteration.
        const int nv4 = (X_DIM - p) >> 2;
        const float4* rp4[ROWS_PER_TASK];
        #pragma unroll
        for (int r = 0; r < ROWS_PER_TASK; r++) {
            rp4[r] = reinterpret_cast<const float4*>(rows[r] + p);
        }

        #pragma unroll 1
        for (int c = lane; c < nv4; c += 32) {
            const int e = p + 4 * c;
            const float xv0 = xs[e + 0];
            const float xv1 = xs[e + 1];
            const float xv2 = xs[e + 2];
            const float xv3 = xs[e + 3];
            #pragma unroll
            for (int r = 0; r < ROWS_PER_TASK; r++) {
                const float4 w = __ldg(rp4[r] + c);
                s[r] = fmaf(w.x, xv0, s[r]);
                s[r] = fmaf(w.y, xv1, s[r]);
                s[r] = fmaf(w.z, xv2, s[r]);
                s[r] = fmaf(w.w, xv3, s[r]);
            }
        }

        // Tail: remaining (X_DIM - p) % 4 elements, scalar, lanes < tail.
        const int tail  = (X_DIM - p) & 3;
        const int start = p + 4 * nv4;
        if (lane < tail) {
            const float xv = xs[start + lane];
            #pragma unroll
            for (int r = 0; r < ROWS_PER_TASK; r++) {
                s[r] = fmaf(__ldg(rows[r] + start + lane), xv, s[r]);
            }
        }

        // Warp-reduce each row, fold relu(h) * W2 on lane 0, one atomic per task.
        const float zk = __ldg(&z[k]);
        float facc = 0.0f;
        #pragma unroll
        for (int r = 0; r < ROWS_PER_TASK; r++) {
            float v = s[r];
            #pragma unroll
            for (int o = 16; o > 0; o >>= 1)
                v += __shfl_xor_sync(0xFFFFFFFFu, v, o);
            if (lane == 0) {
                const int j = m + r * ROW_STRIDE;
                float h = v + __ldg(rows[r] + X_DIM) * zk + __ldg(&b1[k * N_HID + j]);
                facc = fmaf(fmaxf(h, 0.0f), __ldg(&W2[k * N_HID + j]), facc);
            }
        }
        if (lane == 0) atomicAdd(&out[k], facc);
    }
}

extern "C" void kernel_launch(void* const* d_in, const int* in_sizes, int n_in,
                              void* d_out, int out_size) {
    const float* x  = (const float*)d_in[0];
    const float* z  = (const float*)d_in[1];
    const float* W1 = (const float*)d_in[2];
    const float* b1 = (const float*)d_in[3];
    const float* W2 = (const float*)d_in[4];
    const float* b2 = (const float*)d_in[5];
    float* out = (float*)d_out;

    mlp_init_kernel<<<1, 64>>>(b2, out);
    mlp_main_kernel<<<NBLOCKS, THREADS>>>(x, z, W1, b1, W2, out);
}

// round 7
// speedup vs baseline: 1.0023x; 1.0008x over previous
#include <cuda_runtime.h>
#include <cuda_bf16.h>

#define X_DIM 4096
#define Z_DIM 64
#define N_HID 1024
#define ROW_LEN (X_DIM + 1)            // 4097 floats per W1 row
#define THREADS 256
#define NWARPS (THREADS / 32)          // 8
#define NSM 148
#define CTAS_PER_SM 3
#define NBLOCKS (NSM * CTAS_PER_SM)    // 444 — exactly one resident wave
#define ROWS_PER_TASK 8
#define TASKS_PER_HEAD (N_HID / ROWS_PER_TASK)   // 128
#define NTASKS (Z_DIM * TASKS_PER_HEAD)          // 8192
#define ROW_STRIDE TASKS_PER_HEAD      // 128: rows m, m+128, ... share align phase

// 16B vector load, non-coherent, with 256B L2 fetch-granularity hint.
// Rows are consumed contiguously by each warp, so 256B granules are ~fully used.
__device__ __forceinline__ float4 ldg_256B(const float4* p) {
    float4 w;
    asm volatile("ld.global.nc.L2::256B.v4.f32 {%0,%1,%2,%3}, [%4];"
                 : "=f"(w.x), "=f"(w.y), "=f"(w.z), "=f"(w.w)
                 : "l"(p));
    return w;
}

// Seed output with b2 (d_out is poisoned; we atomically accumulate into it).
__global__ void mlp_init_kernel(const float* __restrict__ b2, float* __restrict__ out) {
    int i = threadIdx.x;
    if (i < Z_DIM) out[i] = b2[i];
}

__global__ __launch_bounds__(THREADS, CTAS_PER_SM)
void mlp_main_kernel(const float* __restrict__ x,
                     const float* __restrict__ z,
                     const float* __restrict__ W1,
                     const float* __restrict__ b1,
                     const float* __restrict__ W2,
                     float* __restrict__ out) {
    __shared__ float xs[X_DIM];

    const int tid  = threadIdx.x;
    const int wid  = tid >> 5;
    const int lane = tid & 31;
    const int b    = blockIdx.x;

    // Stage x into shared memory once per block (vectorized, coalesced).
    {
        const float4* x4 = reinterpret_cast<const float4*>(x);
        float4* xs4 = reinterpret_cast<float4*>(xs);
        #pragma unroll
        for (int i = tid; i < X_DIM / 4; i += THREADS) {
            xs4[i] = x4[i];
        }
    }
    __syncthreads();

    // Block-granular task striding: block b owns tasks {b + i*NBLOCKS},
    // round-robined over its 8 warps. One resident wave => ~balanced SMs.
    for (int i = wid; ; i += NWARPS) {
        const int t = b + i * NBLOCKS;
        if (t >= NTASKS) break;

        const int k = t >> 7;            // head index = t / 128
        const int m = t & (TASKS_PER_HEAD - 1);
        const int p = (4 - (m & 3)) & 3; // head peel to reach 16B alignment
        // rows j = m + 128*r share one 16B phase (row start elem = j*4097 ≡ j mod 4)

        const float* rows[ROWS_PER_TASK];
        #pragma unroll
        for (int r = 0; r < ROWS_PER_TASK; r++) {
            rows[r] = W1 + ((size_t)k * N_HID + (m + r * ROW_STRIDE)) * (size_t)ROW_LEN;
        }

        float s[ROWS_PER_TASK];
        #pragma unroll
        for (int r = 0; r < ROWS_PER_TASK; r++) s[r] = 0.0f;

        // Head peel: first p elements (p in 0..3), scalar, lanes < p.
        if (lane < p) {
            const float xv = xs[lane];
            #pragma unroll
            for (int r = 0; r < ROWS_PER_TASK; r++) {
                s[r] = fmaf(__ldg(rows[r] + lane), xv, s[r]);
            }
        }

        // Bulk: aligned float4 streams, 8 independent LDG.128 per iteration,
        // 256B L2 fetch granularity.
        const int nv4 = (X_DIM - p) >> 2;
        const float4* rp4[ROWS_PER_TASK];
        #pragma unroll
        for (int r = 0; r < ROWS_PER_TASK; r++) {
            rp4[r] = reinterpret_cast<const float4*>(rows[r] + p);
        }

        #pragma unroll 1
        for (int c = lane; c < nv4; c += 32) {
            const int e = p + 4 * c;
            const float xv0 = xs[e + 0];
            const float xv1 = xs[e + 1];
            const float xv2 = xs[e + 2];
            const float xv3 = xs[e + 3];
            #pragma unroll
            for (int r = 0; r < ROWS_PER_TASK; r++) {
                const float4 w = ldg_256B(rp4[r] + c);
                s[r] = fmaf(w.x, xv0, s[r]);
                s[r] = fmaf(w.y, xv1, s[r]);
                s[r] = fmaf(w.z, xv2, s[r]);
                s[r] = fmaf(w.w, xv3, s[r]);
            }
        }

        // Tail: remaining (X_DIM - p) % 4 elements, scalar, lanes < tail.
        const int tail  = (X_DIM - p) & 3;
        const int start = p + 4 * nv4;
        if (lane < tail) {
            const float xv = xs[start + lane];
            #pragma unroll
            for (int r = 0; r < ROWS_PER_TASK; r++) {
                s[r] = fmaf(__ldg(rows[r] + start + lane), xv, s[r]);
            }
        }

        // Warp-reduce each row, fold relu(h) * W2 on lane 0, one atomic per task.
        const float zk = __ldg(&z[k]);
        float facc = 0.0f;
        #pragma unroll
        for (int r = 0; r < ROWS_PER_TASK; r++) {
            float v = s[r];
            #pragma unroll
            for (int o = 16; o > 0; o >>= 1)
                v += __shfl_xor_sync(0xFFFFFFFFu, v, o);
            if (lane == 0) {
                const int j = m + r * ROW_STRIDE;
                float h = v + __ldg(rows[r] + X_DIM) * zk + __ldg(&b1[k * N_HID + j]);
                facc = fmaf(fmaxf(h, 0.0f), __ldg(&W2[k * N_HID + j]), facc);
            }
        }
        if (lane == 0) atomicAdd(&out[k], facc);
    }
}

extern "C" void kernel_launch(void* const* d_in, const int* in_sizes, int n_in,
                              void* d_out, int out_size) {
    const float* x  = (const float*)d_in[0];
    const float* z  = (const float*)d_in[1];
    const float* W1 = (const float*)d_in[2];
    const float* b1 = (const float*)d_in[3];
    const float* W2 = (const float*)d_in[4];
    const float* b2 = (const float*)d_in[5];
    float* out = (float*)d_out;

    mlp_init_kernel<<<1, 64>>>(b2, out);
    mlp_main_kernel<<<NBLOCKS, THREADS>>>(x, z, W1, b1, W2, out);
}